// round 11
// baseline (speedup 1.0000x reference)
#include <cuda_runtime.h>
#include <cstdint>

// ----------------------------------------------------------------------------
// Mamba block forward. GEMMs via mma.sync tf32 (arch-portable tensor path).
// B=2, L=1024, D_MODEL=1024, D_INNER=2048, D_STATE=16, DT_RANK=64, D_CONV=4
// ----------------------------------------------------------------------------

#define BATCH   2
#define LSEQ    1024
#define DMODEL  1024
#define DINNER  2048
#define DSTATE  16
#define DTRANK  64
#define XDBLW   (DTRANK + 2*DSTATE)   // 96

// scratch (static device arrays — allocation-free)
__device__ float g_xn   [BATCH*LSEQ*DMODEL];
__device__ float g_xz   [(size_t)BATCH*LSEQ*2*DINNER];
__device__ float g_xc   [BATCH*LSEQ*DINNER];
__device__ float g_xdbl [BATCH*LSEQ*XDBLW];
__device__ float g_dtraw[BATCH*LSEQ*DINNER];
__device__ float g_yout [BATCH*LSEQ*DINNER];
__device__ float g_ybuf [BATCH*LSEQ*DMODEL];

// ============================================================================
// TF32 mma.sync NT GEMM: C[m,n] = sum_k A[m*lda+k] * B[n*ldb+k]
// CTA tile 128x128, BK=16, 256 threads (8 warps, 2x4), warp tile 64x32.
// Optional split-K over blockIdx.z with atomicAdd epilogue.
// M % 128 == 0, K % 16 == 0. N guarded vs Nact (stores need Nact even).
// ============================================================================
#define BM   128
#define BN   128
#define BK   16
#define BKP  20            // smem row stride (floats) — conflict-free
#define TBUF (BM*BKP)      // 2560 floats per tile buffer

__device__ __forceinline__ uint32_t f2tf32(float f) {
    uint32_t u;
    asm("cvt.rna.tf32.f32 %0, %1;" : "=r"(u) : "f"(f));
    return u;
}

__device__ __forceinline__ void mma_tf32(float c[4], uint32_t a0, uint32_t a1,
                                         uint32_t a2, uint32_t a3,
                                         uint32_t b0, uint32_t b1) {
    asm volatile(
        "mma.sync.aligned.m16n8k8.row.col.f32.tf32.tf32.f32 "
        "{%0,%1,%2,%3}, {%4,%5,%6,%7}, {%8,%9}, {%0,%1,%2,%3};"
        : "+f"(c[0]), "+f"(c[1]), "+f"(c[2]), "+f"(c[3])
        : "r"(a0), "r"(a1), "r"(a2), "r"(a3), "r"(b0), "r"(b1));
}

__global__ __launch_bounds__(256)
void gemm_tc(const float* __restrict__ A, int lda,
             const float* __restrict__ B, int ldb,
             float* __restrict__ C, int ldc,
             int Nact, int Ksub, int use_atomic)
{
    __shared__ float sm[4*TBUF];   // A0 B0 A1 B1 -> 40960 bytes

    const int tid  = threadIdx.x;
    const int wid  = tid >> 5;
    const int lane = tid & 31;
    const int g    = lane >> 2;    // 0..7
    const int tg   = lane & 3;     // 0..3
    const int wm   = wid >> 2;     // 0..1
    const int wn   = wid & 3;      // 0..3

    const int bm = blockIdx.y * BM;
    const int bn = blockIdx.x * BN;
    const int koff = blockIdx.z * Ksub;
    const int ntiles = Ksub / BK;

    // global-load mapping: 2 rows per thread, float4 per row
    const int lr  = tid >> 2;        // 0..63
    const int lc4 = (tid & 3) * 4;   // 0,4,8,12

    const float* Ag = A + (size_t)(bm + lr) * lda + koff + lc4;
    const float* Bg = B + (size_t)(bn + lr) * ldb + koff + lc4;
    const size_t lda64 = (size_t)64 * lda;
    const size_t ldb64 = (size_t)64 * ldb;
    const bool bv0 = (bn + lr)      < Nact;
    const bool bv1 = (bn + lr + 64) < Nact;

    float c[4][4][4];
    #pragma unroll
    for (int i = 0; i < 4; ++i)
        #pragma unroll
        for (int j = 0; j < 4; ++j)
            #pragma unroll
            for (int q = 0; q < 4; ++q) c[i][j][q] = 0.f;

    // prologue: fetch chunk 0
    float4 ra0 = *reinterpret_cast<const float4*>(Ag);
    float4 ra1 = *reinterpret_cast<const float4*>(Ag + lda64);
    float4 rb0 = bv0 ? *reinterpret_cast<const float4*>(Bg)
                     : make_float4(0.f,0.f,0.f,0.f);
    float4 rb1 = bv1 ? *reinterpret_cast<const float4*>(Bg + ldb64)
                     : make_float4(0.f,0.f,0.f,0.f);

    // store chunk 0 into buffer 0
    {
        float* As = sm;
        float* Bs = sm + TBUF;
        As[lr*BKP + lc4+0] = __uint_as_float(f2tf32(ra0.x));
        As[lr*BKP + lc4+1] = __uint_as_float(f2tf32(ra0.y));
        As[lr*BKP + lc4+2] = __uint_as_float(f2tf32(ra0.z));
        As[lr*BKP + lc4+3] = __uint_as_float(f2tf32(ra0.w));
        As[(lr+64)*BKP + lc4+0] = __uint_as_float(f2tf32(ra1.x));
        As[(lr+64)*BKP + lc4+1] = __uint_as_float(f2tf32(ra1.y));
        As[(lr+64)*BKP + lc4+2] = __uint_as_float(f2tf32(ra1.z));
        As[(lr+64)*BKP + lc4+3] = __uint_as_float(f2tf32(ra1.w));
        Bs[lr*BKP + lc4+0] = __uint_as_float(f2tf32(rb0.x));
        Bs[lr*BKP + lc4+1] = __uint_as_float(f2tf32(rb0.y));
        Bs[lr*BKP + lc4+2] = __uint_as_float(f2tf32(rb0.z));
        Bs[lr*BKP + lc4+3] = __uint_as_float(f2tf32(rb0.w));
        Bs[(lr+64)*BKP + lc4+0] = __uint_as_float(f2tf32(rb1.x));
        Bs[(lr+64)*BKP + lc4+1] = __uint_as_float(f2tf32(rb1.y));
        Bs[(lr+64)*BKP + lc4+2] = __uint_as_float(f2tf32(rb1.z));
        Bs[(lr+64)*BKP + lc4+3] = __uint_as_float(f2tf32(rb1.w));
    }
    __syncthreads();

    const int arow = wm*64;   // warp A row base within tile
    const int bcol = wn*32;   // warp B row (=C col) base within tile

    for (int t = 0; t < ntiles; ++t) {
        const int cur = t & 1;
        const float* As = sm + cur*2*TBUF;
        const float* Bs = sm + cur*2*TBUF + TBUF;

        // prefetch next chunk
        if (t + 1 < ntiles) {
            const float* Agn = Ag + (t+1)*BK;
            const float* Bgn = Bg + (t+1)*BK;
            ra0 = *reinterpret_cast<const float4*>(Agn);
            ra1 = *reinterpret_cast<const float4*>(Agn + lda64);
            rb0 = bv0 ? *reinterpret_cast<const float4*>(Bgn)
                      : make_float4(0.f,0.f,0.f,0.f);
            rb1 = bv1 ? *reinterpret_cast<const float4*>(Bgn + ldb64)
                      : make_float4(0.f,0.f,0.f,0.f);
        }

        // compute: 2 k-steps of m16n8k8
        #pragma unroll
        for (int ks = 0; ks < 2; ++ks) {
            const int k0 = ks*8;
            uint32_t af[4][4], bf[4][2];
            #pragma unroll
            for (int mt = 0; mt < 4; ++mt) {
                const float* ap = As + (arow + mt*16 + g)*BKP + k0 + tg;
                af[mt][0] = __float_as_uint(ap[0]);
                af[mt][1] = __float_as_uint(ap[8*BKP]);
                af[mt][2] = __float_as_uint(ap[4]);
                af[mt][3] = __float_as_uint(ap[8*BKP + 4]);
            }
            #pragma unroll
            for (int nt = 0; nt < 4; ++nt) {
                const float* bp = Bs + (bcol + nt*8 + g)*BKP + k0 + tg;
                bf[nt][0] = __float_as_uint(bp[0]);
                bf[nt][1] = __float_as_uint(bp[4]);
            }
            #pragma unroll
            for (int mt = 0; mt < 4; ++mt)
                #pragma unroll
                for (int nt = 0; nt < 4; ++nt)
                    mma_tf32(c[mt][nt], af[mt][0], af[mt][1], af[mt][2],
                             af[mt][3], bf[nt][0], bf[nt][1]);
        }

        // store next chunk into other buffer
        if (t + 1 < ntiles) {
            float* An = sm + (cur^1)*2*TBUF;
            float* Bn = sm + (cur^1)*2*TBUF + TBUF;
            An[lr*BKP + lc4+0] = __uint_as_float(f2tf32(ra0.x));
            An[lr*BKP + lc4+1] = __uint_as_float(f2tf32(ra0.y));
            An[lr*BKP + lc4+2] = __uint_as_float(f2tf32(ra0.z));
            An[lr*BKP + lc4+3] = __uint_as_float(f2tf32(ra0.w));
            An[(lr+64)*BKP + lc4+0] = __uint_as_float(f2tf32(ra1.x));
            An[(lr+64)*BKP + lc4+1] = __uint_as_float(f2tf32(ra1.y));
            An[(lr+64)*BKP + lc4+2] = __uint_as_float(f2tf32(ra1.z));
            An[(lr+64)*BKP + lc4+3] = __uint_as_float(f2tf32(ra1.w));
            Bn[lr*BKP + lc4+0] = __uint_as_float(f2tf32(rb0.x));
            Bn[lr*BKP + lc4+1] = __uint_as_float(f2tf32(rb0.y));
            Bn[lr*BKP + lc4+2] = __uint_as_float(f2tf32(rb0.z));
            Bn[lr*BKP + lc4+3] = __uint_as_float(f2tf32(rb0.w));
            Bn[(lr+64)*BKP + lc4+0] = __uint_as_float(f2tf32(rb1.x));
            Bn[(lr+64)*BKP + lc4+1] = __uint_as_float(f2tf32(rb1.y));
            Bn[(lr+64)*BKP + lc4+2] = __uint_as_float(f2tf32(rb1.z));
            Bn[(lr+64)*BKP + lc4+3] = __uint_as_float(f2tf32(rb1.w));
            __syncthreads();
        }
    }

    // epilogue
    #pragma unroll
    for (int mt = 0; mt < 4; ++mt) {
        const int row = bm + arow + mt*16 + g;
        #pragma unroll
        for (int nt = 0; nt < 4; ++nt) {
            const int col = bn + bcol + nt*8 + tg*2;
            if (col >= Nact) continue;   // Nact even -> col+1 also valid
            float* p0 = C + (size_t)row * ldc + col;
            float* p1 = p0 + (size_t)8 * ldc;
            if (use_atomic) {
                atomicAdd(p0,     c[mt][nt][0]);
                atomicAdd(p0 + 1, c[mt][nt][1]);
                atomicAdd(p1,     c[mt][nt][2]);
                atomicAdd(p1 + 1, c[mt][nt][3]);
            } else {
                *reinterpret_cast<float2*>(p0) =
                    make_float2(c[mt][nt][0], c[mt][nt][1]);
                *reinterpret_cast<float2*>(p1) =
                    make_float2(c[mt][nt][2], c[mt][nt][3]);
            }
        }
    }
}

// ---------------------------------------------------------------------------
// zero fill (for split-K atomic output)
// ---------------------------------------------------------------------------
__global__ void zero_kernel(float* __restrict__ p, int n4)
{
    int i = blockIdx.x * blockDim.x + threadIdx.x;
    if (i < n4)
        reinterpret_cast<float4*>(p)[i] = make_float4(0.f, 0.f, 0.f, 0.f);
}

// ---------------------------------------------------------------------------
// LayerNorm + transpose: x (B, C, L) -> xn (B*L, C)
// ---------------------------------------------------------------------------
__global__ void ln_kernel(const float* __restrict__ x,
                          const float* __restrict__ w,
                          const float* __restrict__ b)
{
    __shared__ float red1[32][33];
    __shared__ float red2[32][33];
    __shared__ float mu_s[32], rs_s[32];
    __shared__ float tile[32][33];

    int tx = threadIdx.x, ty = threadIdx.y;
    int l0 = blockIdx.x * 32;
    int bb = blockIdx.y;
    const float* xb = x + (size_t)bb * DMODEL * LSEQ;

    float s1 = 0.f, s2 = 0.f;
    for (int c = ty; c < DMODEL; c += 32) {
        float v = xb[(size_t)c * LSEQ + l0 + tx];
        s1 += v; s2 += v * v;
    }
    red1[ty][tx] = s1; red2[ty][tx] = s2;
    __syncthreads();
    for (int s = 16; s > 0; s >>= 1) {
        if (ty < s) { red1[ty][tx] += red1[ty+s][tx]; red2[ty][tx] += red2[ty+s][tx]; }
        __syncthreads();
    }
    if (ty == 0) {
        float mu  = red1[0][tx] * (1.f / DMODEL);
        float var = red2[0][tx] * (1.f / DMODEL) - mu * mu;
        mu_s[tx] = mu;
        rs_s[tx] = rsqrtf(var + 1e-5f);
    }
    __syncthreads();

    for (int cb = 0; cb < DMODEL/32; ++cb) {
        int c = cb * 32 + ty;
        float v = xb[(size_t)c * LSEQ + l0 + tx];
        tile[ty][tx] = (v - mu_s[tx]) * rs_s[tx] * w[c] + b[c];
        __syncthreads();
        g_xn[(size_t)(bb*LSEQ + l0 + ty) * DMODEL + cb*32 + tx] = tile[tx][ty];
        __syncthreads();
    }
}

// ---------------------------------------------------------------------------
// Depthwise causal conv (width 4) + bias + SiLU.
// ---------------------------------------------------------------------------
__global__ void conv_kernel(const float* __restrict__ cw,
                            const float* __restrict__ cb)
{
    int tid = blockIdx.x * blockDim.x + threadIdx.x;  // 32768 threads
    int d = tid & (DINNER - 1);
    int chunk = tid >> 11;
    int lblk = chunk & 7;
    int bb = chunk >> 3;
    int l0 = lblk * 128;

    float w0 = cw[d*4+0], w1 = cw[d*4+1], w2 = cw[d*4+2], w3 = cw[d*4+3];
    float bias = cb[d];

    const float* src = g_xz + (size_t)bb * LSEQ * (2*DINNER) + d;
    float* dst = g_xc + (size_t)bb * LSEQ * DINNER + d;

    float xm3 = (l0 >= 3) ? src[(size_t)(l0-3) * (2*DINNER)] : 0.f;
    float xm2 = (l0 >= 2) ? src[(size_t)(l0-2) * (2*DINNER)] : 0.f;
    float xm1 = (l0 >= 1) ? src[(size_t)(l0-1) * (2*DINNER)] : 0.f;

    for (int l = l0; l < l0 + 128; ++l) {
        float xl = src[(size_t)l * (2*DINNER)];
        float v = fmaf(w0, xm3, fmaf(w1, xm2, fmaf(w2, xm1, fmaf(w3, xl, bias))));
        float sv = v * __fdividef(1.f, 1.f + __expf(-v));
        dst[(size_t)l * DINNER] = sv;
        xm3 = xm2; xm2 = xm1; xm1 = xl;
    }
}

// ---------------------------------------------------------------------------
// Selective scan. One thread per (b, d, s); 16-lane shfl reduction.
// ---------------------------------------------------------------------------
__global__ void scan_kernel(const float* __restrict__ dtb,
                            const float* __restrict__ A_log,
                            const float* __restrict__ Dp)
{
    int t = blockIdx.x * blockDim.x + threadIdx.x;   // 65536 threads
    int s = t & 15;
    int pair = t >> 4;
    int d = pair & (DINNER - 1);
    int bb = pair >> 11;

    float As = -__expf(A_log[d*DSTATE + s]);
    float Dd = Dp[d];
    float bias = dtb[d];
    float h = 0.f;

    size_t tokbase = (size_t)bb * LSEQ;
    for (int l = 0; l < LSEQ; ++l) {
        size_t token = tokbase + l;
        float dtr = g_dtraw[token*DINNER + d] + bias;
        float dt = (dtr > 20.f) ? dtr : log1pf(__expf(dtr));
        float xcv = g_xc[token*DINNER + d];
        float Bv = g_xdbl[token*XDBLW + DTRANK + s];
        float Cv = g_xdbl[token*XDBLW + DTRANK + DSTATE + s];
        float dA = __expf(dt * As);
        h = fmaf(dA, h, dt * xcv * Bv);
        float acc = h * Cv;
        acc += __shfl_xor_sync(0xffffffffu, acc, 1);
        acc += __shfl_xor_sync(0xffffffffu, acc, 2);
        acc += __shfl_xor_sync(0xffffffffu, acc, 4);
        acc += __shfl_xor_sync(0xffffffffu, acc, 8);
        if (s == 0) {
            float zv = g_xz[token*(2*DINNER) + DINNER + d];
            float sz = zv * __fdividef(1.f, 1.f + __expf(-zv));
            g_yout[token*DINNER + d] = (acc + xcv * Dd) * sz;
        }
    }
}

// ---------------------------------------------------------------------------
// Final: out (B, C, L) = ybuf (B*L, C) transposed + x
// ---------------------------------------------------------------------------
__global__ void outadd_kernel(const float* __restrict__ x, float* __restrict__ out)
{
    __shared__ float tile[32][33];
    int tx = threadIdx.x, ty = threadIdx.y;
    int l0 = blockIdx.x * 32;
    int c0 = blockIdx.y * 32;
    int bb = blockIdx.z;

    tile[ty][tx] = g_ybuf[(size_t)(bb*LSEQ + l0 + ty) * DMODEL + c0 + tx];
    __syncthreads();
    size_t o = (size_t)bb * DMODEL * LSEQ + (size_t)(c0 + ty) * LSEQ + l0 + tx;
    out[o] = tile[tx][ty] + x[o];
}

// ---------------------------------------------------------------------------
extern "C" void kernel_launch(void* const* d_in, const int* in_sizes, int n_in,
                              void* d_out, int out_size)
{
    const float* x          = (const float*)d_in[0];
    const float* ln_w       = (const float*)d_in[1];
    const float* ln_b       = (const float*)d_in[2];
    const float* in_proj_w  = (const float*)d_in[3];
    const float* conv_w     = (const float*)d_in[4];
    const float* conv_b     = (const float*)d_in[5];
    const float* x_proj_w   = (const float*)d_in[6];
    const float* dt_proj_w  = (const float*)d_in[7];
    const float* dt_proj_b  = (const float*)d_in[8];
    const float* A_log      = (const float*)d_in[9];
    const float* Dp         = (const float*)d_in[10];
    const float* out_proj_w = (const float*)d_in[11];
    float* out = (float*)d_out;

    float *p_xn, *p_xz, *p_xc, *p_xdbl, *p_dtraw, *p_yout, *p_ybuf;
    cudaGetSymbolAddress((void**)&p_xn,    g_xn);
    cudaGetSymbolAddress((void**)&p_xz,    g_xz);
    cudaGetSymbolAddress((void**)&p_xc,    g_xc);
    cudaGetSymbolAddress((void**)&p_xdbl,  g_xdbl);
    cudaGetSymbolAddress((void**)&p_dtraw, g_dtraw);
    cudaGetSymbolAddress((void**)&p_yout,  g_yout);
    cudaGetSymbolAddress((void**)&p_ybuf,  g_ybuf);

    const int M = BATCH * LSEQ;   // 2048

    // 1) LayerNorm + transpose
    ln_kernel<<<dim3(LSEQ/32, BATCH), dim3(32, 32)>>>(x, ln_w, ln_b);

    // 2) in_proj: xz[2048, 4096] = xn @ in_proj_w^T   (K=1024)
    gemm_tc<<<dim3((2*DINNER)/BN, M/BM), 256>>>(
        p_xn, DMODEL, in_proj_w, DMODEL, p_xz, 2*DINNER,
        2*DINNER, DMODEL, 0);

    // 3) depthwise conv + SiLU
    conv_kernel<<<128, 256>>>(conv_w, conv_b);

    // 4) x_proj: xdbl[2048, 96] = xc @ x_proj_w^T   (K=2048, split-K=8)
    zero_kernel<<<(M*XDBLW/4 + 255)/256, 256>>>(p_xdbl, M*XDBLW/4);
    gemm_tc<<<dim3(1, M/BM, 8), 256>>>(
        p_xc, DINNER, x_proj_w, DINNER, p_xdbl, XDBLW,
        XDBLW, DINNER/8, 1);

    // 5) dt_proj: dtraw[2048, 2048] = xdbl[:, :64] @ dt_proj_w^T  (K=64)
    gemm_tc<<<dim3(DINNER/BN, M/BM), 256>>>(
        p_xdbl, XDBLW, dt_proj_w, DTRANK, p_dtraw, DINNER,
        DINNER, DTRANK, 0);

    // 6) selective scan (fuses softplus, +x*D, *silu(z))
    scan_kernel<<<256, 256>>>(dt_proj_b, A_log, Dp);

    // 7) out_proj: ybuf[2048, 1024] = yout @ out_proj_w^T  (K=2048)
    gemm_tc<<<dim3(DMODEL/BN, M/BM), 256>>>(
        p_yout, DINNER, out_proj_w, DINNER, p_ybuf, DMODEL,
        DMODEL, DINNER, 0);

    // 8) transpose + residual add
    outadd_kernel<<<dim3(LSEQ/32, DMODEL/32, BATCH), dim3(32, 32)>>>(x, out);
}

// round 15
// speedup vs baseline: 1.0164x; 1.0164x over previous
#include <cuda_runtime.h>
#include <cstdint>

// ----------------------------------------------------------------------------
// Mamba block forward. GEMMs via mma.sync tf32 (arch-portable tensor path).
// B=2, L=1024, D_MODEL=1024, D_INNER=2048, D_STATE=16, DT_RANK=64, D_CONV=4
// ----------------------------------------------------------------------------

#define BATCH   2
#define LSEQ    1024
#define DMODEL  1024
#define DINNER  2048
#define DSTATE  16
#define DTRANK  64
#define XDBLW   (DTRANK + 2*DSTATE)   // 96

// scratch (static device arrays — allocation-free)
__device__ float g_xn   [BATCH*LSEQ*DMODEL];
__device__ float g_xz   [(size_t)BATCH*LSEQ*2*DINNER];
__device__ float g_xc   [BATCH*LSEQ*DINNER];
__device__ float g_xdbl [BATCH*LSEQ*XDBLW];
__device__ float g_dtraw[BATCH*LSEQ*DINNER];
__device__ float g_yout [BATCH*LSEQ*DINNER];
__device__ float g_ybuf [BATCH*LSEQ*DMODEL];

// ============================================================================
// TF32 mma.sync NT GEMM: C[m,n] = sum_k A[m*lda+k] * B[n*ldb+k]
// CTA tile 128x128, BK=16, 256 threads (8 warps, 2x4), warp tile 64x32.
// Optional split-K over blockIdx.z with atomicAdd epilogue.
// M % 128 == 0, K % 16 == 0. N guarded vs Nact (stores need Nact even).
// ============================================================================
#define BM   128
#define BN   128
#define BK   16
#define BKP  20            // smem row stride (floats) — conflict-free
#define TBUF (BM*BKP)      // 2560 floats per tile buffer

__device__ __forceinline__ uint32_t f2tf32(float f) {
    uint32_t u;
    asm("cvt.rna.tf32.f32 %0, %1;" : "=r"(u) : "f"(f));
    return u;
}

__device__ __forceinline__ void mma_tf32(float c[4], uint32_t a0, uint32_t a1,
                                         uint32_t a2, uint32_t a3,
                                         uint32_t b0, uint32_t b1) {
    asm volatile(
        "mma.sync.aligned.m16n8k8.row.col.f32.tf32.tf32.f32 "
        "{%0,%1,%2,%3}, {%4,%5,%6,%7}, {%8,%9}, {%0,%1,%2,%3};"
        : "+f"(c[0]), "+f"(c[1]), "+f"(c[2]), "+f"(c[3])
        : "r"(a0), "r"(a1), "r"(a2), "r"(a3), "r"(b0), "r"(b1));
}

__global__ __launch_bounds__(256)
void gemm_tc(const float* __restrict__ A, int lda,
             const float* __restrict__ B, int ldb,
             float* __restrict__ C, int ldc,
             int Nact, int Ksub, int use_atomic)
{
    __shared__ float sm[4*TBUF];   // A0 B0 A1 B1 -> 40960 bytes

    const int tid  = threadIdx.x;
    const int wid  = tid >> 5;
    const int lane = tid & 31;
    const int g    = lane >> 2;    // 0..7
    const int tg   = lane & 3;     // 0..3
    const int wm   = wid >> 2;     // 0..1
    const int wn   = wid & 3;      // 0..3

    const int bm = blockIdx.y * BM;
    const int bn = blockIdx.x * BN;
    const int koff = blockIdx.z * Ksub;
    const int ntiles = Ksub / BK;

    // global-load mapping: 2 rows per thread, float4 per row
    const int lr  = tid >> 2;        // 0..63
    const int lc4 = (tid & 3) * 4;   // 0,4,8,12

    const float* Ag = A + (size_t)(bm + lr) * lda + koff + lc4;
    const float* Bg = B + (size_t)(bn + lr) * ldb + koff + lc4;
    const size_t lda64 = (size_t)64 * lda;
    const size_t ldb64 = (size_t)64 * ldb;
    const bool bv0 = (bn + lr)      < Nact;
    const bool bv1 = (bn + lr + 64) < Nact;

    float c[4][4][4];
    #pragma unroll
    for (int i = 0; i < 4; ++i)
        #pragma unroll
        for (int j = 0; j < 4; ++j)
            #pragma unroll
            for (int q = 0; q < 4; ++q) c[i][j][q] = 0.f;

    // prologue: fetch chunk 0
    float4 ra0 = *reinterpret_cast<const float4*>(Ag);
    float4 ra1 = *reinterpret_cast<const float4*>(Ag + lda64);
    float4 rb0 = bv0 ? *reinterpret_cast<const float4*>(Bg)
                     : make_float4(0.f,0.f,0.f,0.f);
    float4 rb1 = bv1 ? *reinterpret_cast<const float4*>(Bg + ldb64)
                     : make_float4(0.f,0.f,0.f,0.f);

    // store chunk 0 into buffer 0
    {
        float* As = sm;
        float* Bs = sm + TBUF;
        As[lr*BKP + lc4+0] = __uint_as_float(f2tf32(ra0.x));
        As[lr*BKP + lc4+1] = __uint_as_float(f2tf32(ra0.y));
        As[lr*BKP + lc4+2] = __uint_as_float(f2tf32(ra0.z));
        As[lr*BKP + lc4+3] = __uint_as_float(f2tf32(ra0.w));
        As[(lr+64)*BKP + lc4+0] = __uint_as_float(f2tf32(ra1.x));
        As[(lr+64)*BKP + lc4+1] = __uint_as_float(f2tf32(ra1.y));
        As[(lr+64)*BKP + lc4+2] = __uint_as_float(f2tf32(ra1.z));
        As[(lr+64)*BKP + lc4+3] = __uint_as_float(f2tf32(ra1.w));
        Bs[lr*BKP + lc4+0] = __uint_as_float(f2tf32(rb0.x));
        Bs[lr*BKP + lc4+1] = __uint_as_float(f2tf32(rb0.y));
        Bs[lr*BKP + lc4+2] = __uint_as_float(f2tf32(rb0.z));
        Bs[lr*BKP + lc4+3] = __uint_as_float(f2tf32(rb0.w));
        Bs[(lr+64)*BKP + lc4+0] = __uint_as_float(f2tf32(rb1.x));
        Bs[(lr+64)*BKP + lc4+1] = __uint_as_float(f2tf32(rb1.y));
        Bs[(lr+64)*BKP + lc4+2] = __uint_as_float(f2tf32(rb1.z));
        Bs[(lr+64)*BKP + lc4+3] = __uint_as_float(f2tf32(rb1.w));
    }
    __syncthreads();

    const int arow = wm*64;   // warp A row base within tile
    const int bcol = wn*32;   // warp B row (=C col) base within tile

    for (int t = 0; t < ntiles; ++t) {
        const int cur = t & 1;
        const float* As = sm + cur*2*TBUF;
        const float* Bs = sm + cur*2*TBUF + TBUF;

        // prefetch next chunk
        if (t + 1 < ntiles) {
            const float* Agn = Ag + (t+1)*BK;
            const float* Bgn = Bg + (t+1)*BK;
            ra0 = *reinterpret_cast<const float4*>(Agn);
            ra1 = *reinterpret_cast<const float4*>(Agn + lda64);
            rb0 = bv0 ? *reinterpret_cast<const float4*>(Bgn)
                      : make_float4(0.f,0.f,0.f,0.f);
            rb1 = bv1 ? *reinterpret_cast<const float4*>(Bgn + ldb64)
                      : make_float4(0.f,0.f,0.f,0.f);
        }

        // compute: 2 k-steps of m16n8k8
        #pragma unroll
        for (int ks = 0; ks < 2; ++ks) {
            const int k0 = ks*8;
            uint32_t af[4][4], bf[4][2];
            #pragma unroll
            for (int mt = 0; mt < 4; ++mt) {
                const float* ap = As + (arow + mt*16 + g)*BKP + k0 + tg;
                af[mt][0] = __float_as_uint(ap[0]);
                af[mt][1] = __float_as_uint(ap[8*BKP]);
                af[mt][2] = __float_as_uint(ap[4]);
                af[mt][3] = __float_as_uint(ap[8*BKP + 4]);
            }
            #pragma unroll
            for (int nt = 0; nt < 4; ++nt) {
                const float* bp = Bs + (bcol + nt*8 + g)*BKP + k0 + tg;
                bf[nt][0] = __float_as_uint(bp[0]);
                bf[nt][1] = __float_as_uint(bp[4]);
            }
            #pragma unroll
            for (int mt = 0; mt < 4; ++mt)
                #pragma unroll
                for (int nt = 0; nt < 4; ++nt)
                    mma_tf32(c[mt][nt], af[mt][0], af[mt][1], af[mt][2],
                             af[mt][3], bf[nt][0], bf[nt][1]);
        }

        // store next chunk into other buffer
        if (t + 1 < ntiles) {
            float* An = sm + (cur^1)*2*TBUF;
            float* Bn = sm + (cur^1)*2*TBUF + TBUF;
            An[lr*BKP + lc4+0] = __uint_as_float(f2tf32(ra0.x));
            An[lr*BKP + lc4+1] = __uint_as_float(f2tf32(ra0.y));
            An[lr*BKP + lc4+2] = __uint_as_float(f2tf32(ra0.z));
            An[lr*BKP + lc4+3] = __uint_as_float(f2tf32(ra0.w));
            An[(lr+64)*BKP + lc4+0] = __uint_as_float(f2tf32(ra1.x));
            An[(lr+64)*BKP + lc4+1] = __uint_as_float(f2tf32(ra1.y));
            An[(lr+64)*BKP + lc4+2] = __uint_as_float(f2tf32(ra1.z));
            An[(lr+64)*BKP + lc4+3] = __uint_as_float(f2tf32(ra1.w));
            Bn[lr*BKP + lc4+0] = __uint_as_float(f2tf32(rb0.x));
            Bn[lr*BKP + lc4+1] = __uint_as_float(f2tf32(rb0.y));
            Bn[lr*BKP + lc4+2] = __uint_as_float(f2tf32(rb0.z));
            Bn[lr*BKP + lc4+3] = __uint_as_float(f2tf32(rb0.w));
            Bn[(lr+64)*BKP + lc4+0] = __uint_as_float(f2tf32(rb1.x));
            Bn[(lr+64)*BKP + lc4+1] = __uint_as_float(f2tf32(rb1.y));
            Bn[(lr+64)*BKP + lc4+2] = __uint_as_float(f2tf32(rb1.z));
            Bn[(lr+64)*BKP + lc4+3] = __uint_as_float(f2tf32(rb1.w));
            __syncthreads();
        }
    }

    // epilogue
    #pragma unroll
    for (int mt = 0; mt < 4; ++mt) {
        const int row = bm + arow + mt*16 + g;
        #pragma unroll
        for (int nt = 0; nt < 4; ++nt) {
            const int col = bn + bcol + nt*8 + tg*2;
            if (col >= Nact) continue;   // Nact even -> col+1 also valid
            float* p0 = C + (size_t)row * ldc + col;
            float* p1 = p0 + (size_t)8 * ldc;
            if (use_atomic) {
                atomicAdd(p0,     c[mt][nt][0]);
                atomicAdd(p0 + 1, c[mt][nt][1]);
                atomicAdd(p1,     c[mt][nt][2]);
                atomicAdd(p1 + 1, c[mt][nt][3]);
            } else {
                *reinterpret_cast<float2*>(p0) =
                    make_float2(c[mt][nt][0], c[mt][nt][1]);
                *reinterpret_cast<float2*>(p1) =
                    make_float2(c[mt][nt][2], c[mt][nt][3]);
            }
        }
    }
}

// ---------------------------------------------------------------------------
// zero fill (for split-K atomic output)
// ---------------------------------------------------------------------------
__global__ void zero_kernel(float* __restrict__ p, int n4)
{
    int i = blockIdx.x * blockDim.x + threadIdx.x;
    if (i < n4)
        reinterpret_cast<float4*>(p)[i] = make_float4(0.f, 0.f, 0.f, 0.f);
}

// ---------------------------------------------------------------------------
// LayerNorm + transpose: x (B, C, L) -> xn (B*L, C)
// ---------------------------------------------------------------------------
__global__ void ln_kernel(const float* __restrict__ x,
                          const float* __restrict__ w,
                          const float* __restrict__ b)
{
    __shared__ float red1[32][33];
    __shared__ float red2[32][33];
    __shared__ float mu_s[32], rs_s[32];
    __shared__ float tile[32][33];

    int tx = threadIdx.x, ty = threadIdx.y;
    int l0 = blockIdx.x * 32;
    int bb = blockIdx.y;
    const float* xb = x + (size_t)bb * DMODEL * LSEQ;

    float s1 = 0.f, s2 = 0.f;
    for (int c = ty; c < DMODEL; c += 32) {
        float v = xb[(size_t)c * LSEQ + l0 + tx];
        s1 += v; s2 += v * v;
    }
    red1[ty][tx] = s1; red2[ty][tx] = s2;
    __syncthreads();
    for (int s = 16; s > 0; s >>= 1) {
        if (ty < s) { red1[ty][tx] += red1[ty+s][tx]; red2[ty][tx] += red2[ty+s][tx]; }
        __syncthreads();
    }
    if (ty == 0) {
        float mu  = red1[0][tx] * (1.f / DMODEL);
        float var = red2[0][tx] * (1.f / DMODEL) - mu * mu;
        mu_s[tx] = mu;
        rs_s[tx] = rsqrtf(var + 1e-5f);
    }
    __syncthreads();

    for (int cb = 0; cb < DMODEL/32; ++cb) {
        int c = cb * 32 + ty;
        float v = xb[(size_t)c * LSEQ + l0 + tx];
        tile[ty][tx] = (v - mu_s[tx]) * rs_s[tx] * w[c] + b[c];
        __syncthreads();
        g_xn[(size_t)(bb*LSEQ + l0 + ty) * DMODEL + cb*32 + tx] = tile[tx][ty];
        __syncthreads();
    }
}

// ---------------------------------------------------------------------------
// Depthwise causal conv (width 4) + bias + SiLU.
// ---------------------------------------------------------------------------
__global__ void conv_kernel(const float* __restrict__ cw,
                            const float* __restrict__ cb)
{
    int tid = blockIdx.x * blockDim.x + threadIdx.x;  // 32768 threads
    int d = tid & (DINNER - 1);
    int chunk = tid >> 11;
    int lblk = chunk & 7;
    int bb = chunk >> 3;
    int l0 = lblk * 128;

    float w0 = cw[d*4+0], w1 = cw[d*4+1], w2 = cw[d*4+2], w3 = cw[d*4+3];
    float bias = cb[d];

    const float* src = g_xz + (size_t)bb * LSEQ * (2*DINNER) + d;
    float* dst = g_xc + (size_t)bb * LSEQ * DINNER + d;

    float xm3 = (l0 >= 3) ? src[(size_t)(l0-3) * (2*DINNER)] : 0.f;
    float xm2 = (l0 >= 2) ? src[(size_t)(l0-2) * (2*DINNER)] : 0.f;
    float xm1 = (l0 >= 1) ? src[(size_t)(l0-1) * (2*DINNER)] : 0.f;

    for (int l = l0; l < l0 + 128; ++l) {
        float xl = src[(size_t)l * (2*DINNER)];
        float v = fmaf(w0, xm3, fmaf(w1, xm2, fmaf(w2, xm1, fmaf(w3, xl, bias))));
        float sv = v * __fdividef(1.f, 1.f + __expf(-v));
        dst[(size_t)l * DINNER] = sv;
        xm3 = xm2; xm2 = xm1; xm1 = xl;
    }
}

// ---------------------------------------------------------------------------
// Selective scan. One thread per (b, d, s); 16-lane shfl reduction.
// ---------------------------------------------------------------------------
__global__ void scan_kernel(const float* __restrict__ dtb,
                            const float* __restrict__ A_log,
                            const float* __restrict__ Dp)
{
    int t = blockIdx.x * blockDim.x + threadIdx.x;   // 65536 threads
    int s = t & 15;
    int pair = t >> 4;
    int d = pair & (DINNER - 1);
    int bb = pair >> 11;

    float As = -__expf(A_log[d*DSTATE + s]);
    float Dd = Dp[d];
    float bias = dtb[d];
    float h = 0.f;

    size_t tokbase = (size_t)bb * LSEQ;
    for (int l = 0; l < LSEQ; ++l) {
        size_t token = tokbase + l;
        float dtr = g_dtraw[token*DINNER + d] + bias;
        float dt = (dtr > 20.f) ? dtr : log1pf(__expf(dtr));
        float xcv = g_xc[token*DINNER + d];
        float Bv = g_xdbl[token*XDBLW + DTRANK + s];
        float Cv = g_xdbl[token*XDBLW + DTRANK + DSTATE + s];
        float dA = __expf(dt * As);
        h = fmaf(dA, h, dt * xcv * Bv);
        float acc = h * Cv;
        acc += __shfl_xor_sync(0xffffffffu, acc, 1);
        acc += __shfl_xor_sync(0xffffffffu, acc, 2);
        acc += __shfl_xor_sync(0xffffffffu, acc, 4);
        acc += __shfl_xor_sync(0xffffffffu, acc, 8);
        if (s == 0) {
            float zv = g_xz[token*(2*DINNER) + DINNER + d];
            float sz = zv * __fdividef(1.f, 1.f + __expf(-zv));
            g_yout[token*DINNER + d] = (acc + xcv * Dd) * sz;
        }
    }
}

// ---------------------------------------------------------------------------
// Final: out (B, C, L) = ybuf (B*L, C) transposed + x
// ---------------------------------------------------------------------------
__global__ void outadd_kernel(const float* __restrict__ x, float* __restrict__ out)
{
    __shared__ float tile[32][33];
    int tx = threadIdx.x, ty = threadIdx.y;
    int l0 = blockIdx.x * 32;
    int c0 = blockIdx.y * 32;
    int bb = blockIdx.z;

    tile[ty][tx] = g_ybuf[(size_t)(bb*LSEQ + l0 + ty) * DMODEL + c0 + tx];
    __syncthreads();
    size_t o = (size_t)bb * DMODEL * LSEQ + (size_t)(c0 + ty) * LSEQ + l0 + tx;
    out[o] = tile[tx][ty] + x[o];
}

// ---------------------------------------------------------------------------
extern "C" void kernel_launch(void* const* d_in, const int* in_sizes, int n_in,
                              void* d_out, int out_size)
{
    const float* x          = (const float*)d_in[0];
    const float* ln_w       = (const float*)d_in[1];
    const float* ln_b       = (const float*)d_in[2];
    const float* in_proj_w  = (const float*)d_in[3];
    const float* conv_w     = (const float*)d_in[4];
    const float* conv_b     = (const float*)d_in[5];
    const float* x_proj_w   = (const float*)d_in[6];
    const float* dt_proj_w  = (const float*)d_in[7];
    const float* dt_proj_b  = (const float*)d_in[8];
    const float* A_log      = (const float*)d_in[9];
    const float* Dp         = (const float*)d_in[10];
    const float* out_proj_w = (const float*)d_in[11];
    float* out = (float*)d_out;

    float *p_xn, *p_xz, *p_xc, *p_xdbl, *p_dtraw, *p_yout, *p_ybuf;
    cudaGetSymbolAddress((void**)&p_xn,    g_xn);
    cudaGetSymbolAddress((void**)&p_xz,    g_xz);
    cudaGetSymbolAddress((void**)&p_xc,    g_xc);
    cudaGetSymbolAddress((void**)&p_xdbl,  g_xdbl);
    cudaGetSymbolAddress((void**)&p_dtraw, g_dtraw);
    cudaGetSymbolAddress((void**)&p_yout,  g_yout);
    cudaGetSymbolAddress((void**)&p_ybuf,  g_ybuf);

    const int M = BATCH * LSEQ;   // 2048

    // 1) LayerNorm + transpose
    ln_kernel<<<dim3(LSEQ/32, BATCH), dim3(32, 32)>>>(x, ln_w, ln_b);

    // 2) in_proj: xz[2048, 4096] = xn @ in_proj_w^T   (K=1024)
    gemm_tc<<<dim3((2*DINNER)/BN, M/BM), 256>>>(
        p_xn, DMODEL, in_proj_w, DMODEL, p_xz, 2*DINNER,
        2*DINNER, DMODEL, 0);

    // 3) depthwise conv + SiLU
    conv_kernel<<<128, 256>>>(conv_w, conv_b);

    // 4) x_proj: xdbl[2048, 96] = xc @ x_proj_w^T   (K=2048, split-K=8)
    zero_kernel<<<(M*XDBLW/4 + 255)/256, 256>>>(p_xdbl, M*XDBLW/4);
    gemm_tc<<<dim3(1, M/BM, 8), 256>>>(
        p_xc, DINNER, x_proj_w, DINNER, p_xdbl, XDBLW,
        XDBLW, DINNER/8, 1);

    // 5) dt_proj: dtraw[2048, 2048] = xdbl[:, :64] @ dt_proj_w^T  (K=64)
    gemm_tc<<<dim3(DINNER/BN, M/BM), 256>>>(
        p_xdbl, XDBLW, dt_proj_w, DTRANK, p_dtraw, DINNER,
        DINNER, DTRANK, 0);

    // 6) selective scan (fuses softplus, +x*D, *silu(z))
    scan_kernel<<<256, 256>>>(dt_proj_b, A_log, Dp);

    // 7) out_proj: ybuf[2048, 1024] = yout @ out_proj_w^T  (K=2048)
    gemm_tc<<<dim3(DMODEL/BN, M/BM), 256>>>(
        p_yout, DINNER, out_proj_w, DINNER, p_ybuf, DMODEL,
        DMODEL, DINNER, 0);

    // 8) transpose + residual add
    outadd_kernel<<<dim3(LSEQ/32, DMODEL/32, BATCH), dim3(32, 32)>>>(x, out);
}